// round 16
// baseline (speedup 1.0000x reference)
#include <cuda_runtime.h>
#include <cuda_bf16.h>
#include <cstdint>
#include <math.h>

// Problem constants
#define B_    8192
#define C_    512
#define F_    8
#define COUP_ 1024
#define NBL_  2
#define D1_   256
#define D2_   256

// ---------------------------------------------------------------------------
// Scratch (device globals — no allocations allowed)
// ---------------------------------------------------------------------------
__device__ float g_X0[B_ * C_];
__device__ float g_X1[B_ * C_];
__device__ float g_LD[B_];
__device__ float g_scale[F_ * C_];
__device__ float g_lssum[F_];

// x-path weights: split-bf16 (G1 stays high precision)
__device__ __nv_bfloat16 g_Wph[F_ * C_ * C_], g_Wpl[F_ * C_ * C_];
// subnet weights: tf32-rounded fp32 (wo ROW-PERMUTED: new 2j = s_j, 2j+1 = t_j)
__device__ float g_w032[F_ * COUP_ * D1_];
__device__ float g_wh32[F_ * NBL_ * COUP_ * COUP_];
__device__ float g_wo32[F_ * 2 * D2_ * COUP_];

// activations: XF split-bf16 ping-pong (x-path); subnet fp32 (tf32-rounded)
__device__ __nv_bfloat16 g_XF0h[B_ * C_], g_XF0l[B_ * C_];
__device__ __nv_bfloat16 g_XF1h[B_ * C_], g_XF1l[B_ * C_];
__device__ float g_XA32[B_ * D1_];
__device__ float g_HA32[B_ * COUP_];
__device__ float g_HB32[B_ * COUP_];

// ---------------------------------------------------------------------------
// Helpers
// ---------------------------------------------------------------------------
__device__ __forceinline__ uint32_t smem_u32(const void* p) {
    uint32_t a;
    asm("{ .reg .u64 t; cvta.to.shared.u64 t, %1; cvt.u32.u64 %0, t; }" : "=r"(a) : "l"(p));
    return a;
}
__device__ __forceinline__ void cpasync16(uint32_t s, const void* g) {
    asm volatile("cp.async.cg.shared.global [%0], [%1], 16;" :: "r"(s), "l"(g) : "memory");
}
__device__ __forceinline__ void cp_commit() { asm volatile("cp.async.commit_group;" ::: "memory"); }
__device__ __forceinline__ void cp_wait0()  { asm volatile("cp.async.wait_group 0;" ::: "memory"); }
__device__ __forceinline__ void cp_wait1()  { asm volatile("cp.async.wait_group 1;" ::: "memory"); }
__device__ __forceinline__ void ldsm4(uint32_t* r, uint32_t addr) {
    asm volatile("ldmatrix.sync.aligned.m8n8.x4.shared.b16 {%0,%1,%2,%3}, [%4];"
                 : "=r"(r[0]), "=r"(r[1]), "=r"(r[2]), "=r"(r[3]) : "r"(addr));
}
__device__ __forceinline__ void mma16816(float* d, const uint32_t* a, const uint32_t* b) {
    asm("mma.sync.aligned.m16n8k16.row.col.f32.bf16.bf16.f32 "
        "{%0,%1,%2,%3}, {%4,%5,%6,%7}, {%8,%9}, {%0,%1,%2,%3};"
        : "+f"(d[0]), "+f"(d[1]), "+f"(d[2]), "+f"(d[3])
        : "r"(a[0]), "r"(a[1]), "r"(a[2]), "r"(a[3]), "r"(b[0]), "r"(b[1]));
}
__device__ __forceinline__ void mma1688t(float* d, const uint32_t* a, const uint32_t* b) {
    asm("mma.sync.aligned.m16n8k8.row.col.f32.tf32.tf32.f32 "
        "{%0,%1,%2,%3}, {%4,%5,%6,%7}, {%8,%9}, {%0,%1,%2,%3};"
        : "+f"(d[0]), "+f"(d[1]), "+f"(d[2]), "+f"(d[3])
        : "r"(a[0]), "r"(a[1]), "r"(a[2]), "r"(a[3]), "r"(b[0]), "r"(b[1]));
}
__device__ __forceinline__ uint32_t pk2(__nv_bfloat16 a, __nv_bfloat16 b) {
    return (uint32_t)__bfloat16_as_ushort(a) | ((uint32_t)__bfloat16_as_ushort(b) << 16);
}
__device__ __forceinline__ void split_store(__nv_bfloat16* hp, __nv_bfloat16* lp,
                                            float a, float b) {
    __nv_bfloat16 ha = __float2bfloat16(a), hb = __float2bfloat16(b);
    *(uint32_t*)hp = pk2(ha, hb);
    *(uint32_t*)lp = pk2(__float2bfloat16(a - __bfloat162float(ha)),
                         __float2bfloat16(b - __bfloat162float(hb)));
}
__device__ __forceinline__ float tf32r(float x) {
    uint32_t u = __float_as_uint(x), o;
    asm("cvt.rna.tf32.f32 %0, %1;" : "=r"(o) : "r"(u));
    return __uint_as_float(o);
}

// smem: both paths use 32KB stages, 3 stages + 512B bias = 98816 -> 2 CTAs/SM
#define TILE_BYTES 8192
#define STAGE_BYTES 32768
#define SM_BIAS_OFF (3 * STAGE_BYTES)
#define SM_TOTAL (SM_BIAS_OFF + 512)

// tf32 smem addressing: 128 rows x 32 fp32 (128B/row); 16B chunk rotation (q+row)&7
__device__ __forceinline__ uint32_t taddr(int row, int kcol) {
    return (uint32_t)(row * 128 + ((((kcol >> 2) + row) & 7) << 4) + ((kcol & 3) << 2));
}

// ---------------------------------------------------------------------------
// G1: split-bf16 GEMM (x-path). X = XF @ Wp^T.
// ---------------------------------------------------------------------------
__global__ __launch_bounds__(256)
void g1_gemm(const __nv_bfloat16* __restrict__ Ah, const __nv_bfloat16* __restrict__ Al,
             const __nv_bfloat16* __restrict__ Bh, const __nv_bfloat16* __restrict__ Bl,
             float* __restrict__ Yf,
             const float* __restrict__ scn, const float* __restrict__ offn,
             __nv_bfloat16* __restrict__ xfnh, __nv_bfloat16* __restrict__ xfnl,
             float* __restrict__ outp, int last) {
    extern __shared__ char smem[];
    const uint32_t sb = smem_u32(smem);
    const int tid  = threadIdx.x;
    const int lane = tid & 31;
    const int wid  = tid >> 5;
    const int warp_m = wid & 3;
    const int warp_n = wid >> 2;
    const int m0 = blockIdx.y * 128;
    const int n0 = blockIdx.x * 128;
    const int K = C_;

    float acc[2][8][4];
#pragma unroll
    for (int mt = 0; mt < 2; mt++)
#pragma unroll
        for (int nt = 0; nt < 8; nt++)
#pragma unroll
            for (int q = 0; q < 4; q++) acc[mt][nt][q] = 0.0f;

    const int nchunks = K >> 5;

    auto prefetch = [&](int st, int kb) {
        uint32_t base = sb + st * STAGE_BYTES;
#pragma unroll
        for (int i = 0; i < 2; i++) {
            int v = tid + i * 256;
            int r = v >> 2, c = v & 3;
            uint32_t sw = (uint32_t)((c ^ ((r >> 1) & 3)) << 4) + r * 64;
            size_t ga = (size_t)(m0 + r) * K + kb + c * 8;
            size_t gb = (size_t)(n0 + r) * K + kb + c * 8;
            cpasync16(base + sw,                  Ah + ga);
            cpasync16(base + TILE_BYTES + sw,     Al + ga);
            cpasync16(base + 2 * TILE_BYTES + sw, Bh + gb);
            cpasync16(base + 3 * TILE_BYTES + sw, Bl + gb);
        }
        cp_commit();
    };

    auto compute = [&](int st) {
        uint32_t base = sb + st * STAGE_BYTES;
#pragma unroll
        for (int ks = 0; ks < 2; ks++) {
            uint32_t ah[2][4], al_[2][4];
#pragma unroll
            for (int mt = 0; mt < 2; mt++) {
                int gq  = lane >> 3;
                int row = warp_m * 32 + mt * 16 + (lane & 7) + (gq & 1) * 8;
                int ch  = ks * 2 + (gq >> 1);
                uint32_t o = row * 64 + ((ch ^ ((row >> 1) & 3)) << 4);
                ldsm4(ah[mt],  base + o);
                ldsm4(al_[mt], base + TILE_BYTES + o);
            }
            uint32_t bh_[4][4], bl_[4][4];
#pragma unroll
            for (int nt = 0; nt < 4; nt++) {
                int row = warp_n * 64 + nt * 16 + (lane & 7) + ((lane >> 4) & 1) * 8;
                int ch  = ks * 2 + ((lane >> 3) & 1);
                uint32_t o = row * 64 + ((ch ^ ((row >> 1) & 3)) << 4);
                ldsm4(bh_[nt], base + 2 * TILE_BYTES + o);
                ldsm4(bl_[nt], base + 3 * TILE_BYTES + o);
            }
#pragma unroll
            for (int mt = 0; mt < 2; mt++)
#pragma unroll
                for (int nt = 0; nt < 4; nt++)
#pragma unroll
                    for (int hf = 0; hf < 2; hf++)
                        mma16816(acc[mt][nt * 2 + hf], ah[mt], &bh_[nt][hf * 2]);
#pragma unroll
            for (int mt = 0; mt < 2; mt++)
#pragma unroll
                for (int nt = 0; nt < 4; nt++)
#pragma unroll
                    for (int hf = 0; hf < 2; hf++)
                        mma16816(acc[mt][nt * 2 + hf], ah[mt], &bl_[nt][hf * 2]);
#pragma unroll
            for (int mt = 0; mt < 2; mt++)
#pragma unroll
                for (int nt = 0; nt < 4; nt++)
#pragma unroll
                    for (int hf = 0; hf < 2; hf++)
                        mma16816(acc[mt][nt * 2 + hf], al_[mt], &bh_[nt][hf * 2]);
        }
    };

    prefetch(0, 0);
    prefetch(1, 32);
    for (int kc = 0; kc < nchunks; kc++) {
        if (kc + 1 < nchunks) cp_wait1();
        else                  cp_wait0();
        __syncthreads();
        if (kc + 2 < nchunks) prefetch((kc + 2) % 3, (kc + 2) * 32);
        compute(kc % 3);
    }

    const int qr  = lane >> 2;
    const int qc2 = (lane & 3) * 2;
#pragma unroll
    for (int mt = 0; mt < 2; mt++) {
        int r0 = m0 + warp_m * 32 + mt * 16 + qr;
        int r1 = r0 + 8;
#pragma unroll
        for (int nt = 0; nt < 8; nt++) {
            float* d = acc[mt][nt];
            int col_g = n0 + warp_n * 64 + nt * 8 + qc2;
            float v00 = d[0], v01 = d[1], v10 = d[2], v11 = d[3];
            *(float2*)(Yf + (size_t)r0 * C_ + col_g) = make_float2(v00, v01);
            *(float2*)(Yf + (size_t)r1 * C_ + col_g) = make_float2(v10, v11);
            if (last) {
                *(float2*)(outp + (size_t)r0 * C_ + col_g) = make_float2(v00, v01);
                *(float2*)(outp + (size_t)r1 * C_ + col_g) = make_float2(v10, v11);
            }
            if (col_g < D1_) {
                *(float2*)(g_XA32 + (size_t)r0 * D1_ + col_g) = make_float2(tf32r(v00), tf32r(v01));
                *(float2*)(g_XA32 + (size_t)r1 * D1_ + col_g) = make_float2(tf32r(v10), tf32r(v11));
                if (!last) {
                    float u00 = fmaf(v00, scn[col_g],     offn[col_g]);
                    float u01 = fmaf(v01, scn[col_g + 1], offn[col_g + 1]);
                    float u10 = fmaf(v10, scn[col_g],     offn[col_g]);
                    float u11 = fmaf(v11, scn[col_g + 1], offn[col_g + 1]);
                    split_store(xfnh + (size_t)r0 * C_ + col_g, xfnl + (size_t)r0 * C_ + col_g, u00, u01);
                    split_store(xfnh + (size_t)r1 * C_ + col_g, xfnl + (size_t)r1 * C_ + col_g, u10, u11);
                }
            }
        }
    }
}

// ---------------------------------------------------------------------------
// tf32 GEMM: MODE 1 = relu + tf32 out; MODE 2 = fused coupling epilogue
// ---------------------------------------------------------------------------
template <int MODE>
__global__ __launch_bounds__(256)
void tf_gemm(const float* __restrict__ A, const float* __restrict__ Bp,
             const float* __restrict__ bias,
             float* __restrict__ Yf, int ldy, int K,
             const float* __restrict__ scn, const float* __restrict__ offn,
             __nv_bfloat16* __restrict__ xfnh, __nv_bfloat16* __restrict__ xfnl,
             const float* __restrict__ Xc,
             float* __restrict__ outp, int last) {
    extern __shared__ char smem[];
    const uint32_t sb = smem_u32(smem);
    const int tid  = threadIdx.x;
    const int lane = tid & 31;
    const int wid  = tid >> 5;
    const int warp_m = wid & 3;
    const int warp_n = wid >> 2;
    const int m0 = blockIdx.y * 128;
    const int n0 = blockIdx.x * 128;
    const int g  = lane >> 2;
    const int tig = lane & 3;

    float* bias_s = (float*)(smem + SM_BIAS_OFF);
    for (int j = tid; j < 128; j += 256) {
        if (MODE == 2) {
            int rn = n0 + j;
            int old = (rn & 1) ? ((rn >> 1) + 256) : (rn >> 1);
            bias_s[j] = bias[old];
        } else {
            bias_s[j] = bias[n0 + j];
        }
    }

    float acc[2][8][4];
#pragma unroll
    for (int mt = 0; mt < 2; mt++)
#pragma unroll
        for (int nt = 0; nt < 8; nt++)
#pragma unroll
            for (int q = 0; q < 4; q++) acc[mt][nt][q] = 0.0f;

    const int nchunks = K >> 5;

    auto prefetch = [&](int st, int kb) {
        uint32_t base = sb + st * STAGE_BYTES;
#pragma unroll
        for (int i = 0; i < 4; i++) {
            int v = tid + i * 256;
            int r = v >> 3, q = v & 7;
            uint32_t dst = (uint32_t)(r * 128 + (((q + r) & 7) << 4));
            cpasync16(base + dst,         A  + (size_t)(m0 + r) * K + kb + q * 4);
            cpasync16(base + 16384 + dst, Bp + (size_t)(n0 + r) * K + kb + q * 4);
        }
        cp_commit();
    };

    auto compute = [&](int st) {
        uint32_t baseA = sb + st * STAGE_BYTES;
        uint32_t baseB = baseA + 16384;
#pragma unroll
        for (int ks = 0; ks < 4; ks++) {
            int k0 = ks * 8 + tig, k2 = k0 + 4;
            uint32_t a[2][4];
#pragma unroll
            for (int mt = 0; mt < 2; mt++) {
                int r = warp_m * 32 + mt * 16 + g;
                a[mt][0] = *(const uint32_t*)(smem + (baseA - sb) + taddr(r,     k0));
                a[mt][1] = *(const uint32_t*)(smem + (baseA - sb) + taddr(r + 8, k0));
                a[mt][2] = *(const uint32_t*)(smem + (baseA - sb) + taddr(r,     k2));
                a[mt][3] = *(const uint32_t*)(smem + (baseA - sb) + taddr(r + 8, k2));
            }
            uint32_t b[8][2];
#pragma unroll
            for (int nt = 0; nt < 8; nt++) {
                int r = warp_n * 64 + nt * 8 + g;
                b[nt][0] = *(const uint32_t*)(smem + (baseB - sb) + taddr(r, k0));
                b[nt][1] = *(const uint32_t*)(smem + (baseB - sb) + taddr(r, k2));
            }
#pragma unroll
            for (int mt = 0; mt < 2; mt++)
#pragma unroll
                for (int nt = 0; nt < 8; nt++)
                    mma1688t(acc[mt][nt], a[mt], b[nt]);
        }
    };

    prefetch(0, 0);
    prefetch(1, 32);
    for (int kc = 0; kc < nchunks; kc++) {
        if (kc + 1 < nchunks) cp_wait1();
        else                  cp_wait0();
        __syncthreads();
        if (kc + 2 < nchunks) prefetch((kc + 2) % 3, (kc + 2) * 32);
        compute(kc % 3);
    }

    const int qr  = lane >> 2;
    const int qc2 = (lane & 3) * 2;
#pragma unroll
    for (int mt = 0; mt < 2; mt++) {
        int r0 = m0 + warp_m * 32 + mt * 16 + qr;
        int r1 = r0 + 8;
        float sum_s0 = 0.0f, sum_s1 = 0.0f;
#pragma unroll
        for (int nt = 0; nt < 8; nt++) {
            float* d = acc[mt][nt];
            int col_l = warp_n * 64 + nt * 8 + qc2;
            int col_g = n0 + col_l;
            if (MODE == 2) {
                int jg = col_g >> 1;
                float bs = bias_s[col_l], bt = bias_s[col_l + 1];
                float s0 = 2.0f * tanhf((d[0] + bs) * 0.1f);
                float t0 = (d[1] + bt) * 0.1f;
                float s1 = 2.0f * tanhf((d[2] + bs) * 0.1f);
                float t1 = (d[3] + bt) * 0.1f;
                float nx0 = Xc[(size_t)r0 * C_ + D1_ + jg] * expf(s0) + t0;
                float nx1 = Xc[(size_t)r1 * C_ + D1_ + jg] * expf(s1) + t1;
                sum_s0 += s0;
                sum_s1 += s1;
                if (!last) {
                    float u0 = fmaf(nx0, scn[D1_ + jg], offn[D1_ + jg]);
                    float u1 = fmaf(nx1, scn[D1_ + jg], offn[D1_ + jg]);
                    __nv_bfloat16 h0 = __float2bfloat16(u0);
                    __nv_bfloat16 h1 = __float2bfloat16(u1);
                    xfnh[(size_t)r0 * C_ + D1_ + jg] = h0;
                    xfnh[(size_t)r1 * C_ + D1_ + jg] = h1;
                    xfnl[(size_t)r0 * C_ + D1_ + jg] = __float2bfloat16(u0 - __bfloat162float(h0));
                    xfnl[(size_t)r1 * C_ + D1_ + jg] = __float2bfloat16(u1 - __bfloat162float(h1));
                } else {
                    outp[(size_t)r0 * C_ + D1_ + jg] = nx0;
                    outp[(size_t)r1 * C_ + D1_ + jg] = nx1;
                }
            } else {
                float bb0 = bias_s[col_l], bb1 = bias_s[col_l + 1];
                float v00 = fmaxf(d[0] + bb0, 0.0f), v01 = fmaxf(d[1] + bb1, 0.0f);
                float v10 = fmaxf(d[2] + bb0, 0.0f), v11 = fmaxf(d[3] + bb1, 0.0f);
                *(float2*)(Yf + (size_t)r0 * ldy + col_g) = make_float2(tf32r(v00), tf32r(v01));
                *(float2*)(Yf + (size_t)r1 * ldy + col_g) = make_float2(tf32r(v10), tf32r(v11));
            }
        }
        if (MODE == 2) {
            sum_s0 += __shfl_xor_sync(0xFFFFFFFFu, sum_s0, 1);
            sum_s0 += __shfl_xor_sync(0xFFFFFFFFu, sum_s0, 2);
            sum_s1 += __shfl_xor_sync(0xFFFFFFFFu, sum_s1, 1);
            sum_s1 += __shfl_xor_sync(0xFFFFFFFFu, sum_s1, 2);
            if ((lane & 3) == 0) {
                atomicAdd(g_LD + r0, sum_s0);
                atomicAdd(g_LD + r1, sum_s1);
            }
        }
    }
}

// ---------------------------------------------------------------------------
// Prep kernels (vectorized float4; merged)
// ---------------------------------------------------------------------------
#define N_WP (F_ * C_ * C_)
#define N_W0 (F_ * COUP_ * D1_)
#define N_WH (F_ * NBL_ * COUP_ * COUP_)
#define N_WO (F_ * 2 * D2_ * COUP_)
#define N_ALLW (N_WP + N_W0 + N_WH + N_WO)

__global__ void prep_weights_kernel(const float* __restrict__ Wp,
                                    const float* __restrict__ w0,
                                    const float* __restrict__ wh,
                                    const float* __restrict__ wo) {
    int i = blockIdx.x * blockDim.x + threadIdx.x;
    int i4 = i * 4;
    if (i4 >= N_ALLW) return;
    int j = i4;
    if (j < N_WP) {
        float4 v = *(const float4*)(Wp + j);
        __nv_bfloat16 h0 = __float2bfloat16(v.x), h1 = __float2bfloat16(v.y);
        __nv_bfloat16 h2 = __float2bfloat16(v.z), h3 = __float2bfloat16(v.w);
        *(uint2*)(g_Wph + j) = make_uint2(pk2(h0, h1), pk2(h2, h3));
        *(uint2*)(g_Wpl + j) = make_uint2(
            pk2(__float2bfloat16(v.x - __bfloat162float(h0)),
                __float2bfloat16(v.y - __bfloat162float(h1))),
            pk2(__float2bfloat16(v.z - __bfloat162float(h2)),
                __float2bfloat16(v.w - __bfloat162float(h3))));
    } else if ((j -= N_WP) < N_W0) {
        float4 v = *(const float4*)(w0 + j);
        *(float4*)(g_w032 + j) = make_float4(tf32r(v.x), tf32r(v.y), tf32r(v.z), tf32r(v.w));
    } else if ((j -= N_W0) < N_WH) {
        float4 v = *(const float4*)(wh + j);
        *(float4*)(g_wh32 + j) = make_float4(tf32r(v.x), tf32r(v.y), tf32r(v.z), tf32r(v.w));
    } else {
        j -= N_WH;
        int f = j / (2 * D2_ * COUP_);
        int rem = j % (2 * D2_ * COUP_);
        int row = rem / COUP_, col = rem % COUP_;
        int rnew = (row < D2_) ? (2 * row) : (2 * (row - D2_) + 1);
        float4 v = *(const float4*)(wo + j);
        *(float4*)(g_wo32 + (size_t)f * 2 * D2_ * COUP_ + (size_t)rnew * COUP_ + col) =
            make_float4(tf32r(v.x), tf32r(v.y), tf32r(v.z), tf32r(v.w));
    }
}

__global__ void prep_scale_kernel(const float* __restrict__ g) {
    int f = blockIdx.x;
    int c = threadIdx.x;
    float gv = g[f * C_ + c];
    float sc = 0.2f * log1pf(expf(0.5f * gv));
    g_scale[f * C_ + c] = sc;
    __shared__ float red[C_];
    red[c] = logf(sc);
    __syncthreads();
    for (int s = C_ / 2; s > 0; s >>= 1) {
        if (c < s) red[c] += red[c + s];
        __syncthreads();
    }
    if (c == 0) g_lssum[f] = red[0];
}

// flow-0 input prep (vectorized) + LD zeroing
__global__ void prep0_full_kernel(const float* __restrict__ z0,
                                  const float* __restrict__ off0) {
    int i = blockIdx.x * blockDim.x + threadIdx.x;
    if (i < B_) g_LD[i] = 0.0f;
    int i4 = i * 4;
    if (i4 < B_ * C_) {
        int c = i4 & (C_ - 1);
        float4 z = *(const float4*)(z0 + i4);
        float4 o = *(const float4*)(off0 + c);
        float4 s = *(const float4*)(g_scale + c);
        float v0 = fmaf(z.x, s.x, o.x), v1 = fmaf(z.y, s.y, o.y);
        float v2 = fmaf(z.z, s.z, o.z), v3 = fmaf(z.w, s.w, o.w);
        __nv_bfloat16 h0 = __float2bfloat16(v0), h1 = __float2bfloat16(v1);
        __nv_bfloat16 h2 = __float2bfloat16(v2), h3 = __float2bfloat16(v3);
        *(uint2*)(g_XF0h + i4) = make_uint2(pk2(h0, h1), pk2(h2, h3));
        *(uint2*)(g_XF0l + i4) = make_uint2(
            pk2(__float2bfloat16(v0 - __bfloat162float(h0)),
                __float2bfloat16(v1 - __bfloat162float(h1))),
            pk2(__float2bfloat16(v2 - __bfloat162float(h2)),
                __float2bfloat16(v3 - __bfloat162float(h3))));
    }
}

__global__ void finalize_ld_kernel(float* __restrict__ out) {
    int r = blockIdx.x * blockDim.x + threadIdx.x;
    if (r < B_) {
        float ls = 0.0f;
#pragma unroll
        for (int f = 0; f < F_; f++) ls += g_lssum[f];
        out[(size_t)B_ * C_ + r] = g_LD[r] + ls;
    }
}

// ---------------------------------------------------------------------------
extern "C" void kernel_launch(void* const* d_in, const int* in_sizes, int n_in,
                              void* d_out, int out_size) {
    const float* z0  = (const float*)d_in[0];
    const float* Wp  = (const float*)d_in[1];
    const float* g   = (const float*)d_in[2];
    const float* off = (const float*)d_in[3];
    const float* w0  = (const float*)d_in[4];
    const float* b0  = (const float*)d_in[5];
    const float* wh  = (const float*)d_in[6];
    const float* bh  = (const float*)d_in[7];
    const float* wo  = (const float*)d_in[8];
    const float* bo  = (const float*)d_in[9];
    float* out = (float*)d_out;

    float *X0, *X1, *scaleP, *XA32, *HA32, *HB32, *w032, *wh32, *wo32;
    __nv_bfloat16 *Wph, *Wpl, *XF0h, *XF0l, *XF1h, *XF1l;
    cudaGetSymbolAddress((void**)&X0, g_X0);
    cudaGetSymbolAddress((void**)&X1, g_X1);
    cudaGetSymbolAddress((void**)&scaleP, g_scale);
    cudaGetSymbolAddress((void**)&Wph, g_Wph); cudaGetSymbolAddress((void**)&Wpl, g_Wpl);
    cudaGetSymbolAddress((void**)&w032, g_w032);
    cudaGetSymbolAddress((void**)&wh32, g_wh32);
    cudaGetSymbolAddress((void**)&wo32, g_wo32);
    cudaGetSymbolAddress((void**)&XF0h, g_XF0h); cudaGetSymbolAddress((void**)&XF0l, g_XF0l);
    cudaGetSymbolAddress((void**)&XF1h, g_XF1h); cudaGetSymbolAddress((void**)&XF1l, g_XF1l);
    cudaGetSymbolAddress((void**)&XA32, g_XA32);
    cudaGetSymbolAddress((void**)&HA32, g_HA32);
    cudaGetSymbolAddress((void**)&HB32, g_HB32);

    cudaFuncSetAttribute(g1_gemm,    cudaFuncAttributeMaxDynamicSharedMemorySize, SM_TOTAL);
    cudaFuncSetAttribute(tf_gemm<1>, cudaFuncAttributeMaxDynamicSharedMemorySize, SM_TOTAL);
    cudaFuncSetAttribute(tf_gemm<2>, cudaFuncAttributeMaxDynamicSharedMemorySize, SM_TOTAL);

    // launch order: 0=prep_scale, 1=prep_weights, 2=prep0,
    //               3=G1, 4=G2, 5=G3 (ncu -s 5 -c 1 lands on the dominant GEMM)
    prep_scale_kernel<<<F_, C_>>>(g);
    prep_weights_kernel<<<(N_ALLW / 4 + 255) / 256, 256>>>(Wp, w0, wh, wo);
    prep0_full_kernel<<<(B_ * C_ / 4 + 255) / 256, 256>>>(z0, off);

    for (int f = 0; f < F_; f++) {
        float* Xcur = (f & 1) ? X1 : X0;
        __nv_bfloat16* XFih = (f & 1) ? XF1h : XF0h;
        __nv_bfloat16* XFil = (f & 1) ? XF1l : XF0l;
        __nv_bfloat16* XFnh = (f & 1) ? XF0h : XF1h;
        __nv_bfloat16* XFnl = (f & 1) ? XF0l : XF1l;

        const __nv_bfloat16* Wph_f = Wph + (size_t)f * C_ * C_;
        const __nv_bfloat16* Wpl_f = Wpl + (size_t)f * C_ * C_;
        const float* w0_f  = w032 + (size_t)f * COUP_ * D1_;
        const float* wh_f0 = wh32 + (size_t)f * NBL_ * COUP_ * COUP_;
        const float* wh_f1 = wh_f0 + (size_t)COUP_ * COUP_;
        const float* wo_f  = wo32 + (size_t)f * 2 * D2_ * COUP_;
        const float* b0_f  = b0 + (size_t)f * COUP_;
        const float* bh_f0 = bh + (size_t)f * NBL_ * COUP_;
        const float* bh_f1 = bh_f0 + COUP_;
        const float* bo_f  = bo + (size_t)f * 2 * D2_;

        int last = (f == F_ - 1) ? 1 : 0;
        const float* sc_n  = scaleP + (size_t)((f + 1) % F_) * C_;
        const float* off_n = off + (size_t)((f + 1) % F_) * C_;

        // 1) G1 (split-bf16): X = XF @ Wp^T
        g1_gemm<<<dim3(C_ / 128, B_ / 128), 256, SM_TOTAL>>>(
            XFih, XFil, Wph_f, Wpl_f, Xcur,
            sc_n, off_n, XFnh, XFnl, out, last);

        // 2) G2 (tf32): HA = relu(x1 @ w0^T + b0), K=256
        tf_gemm<1><<<dim3(COUP_ / 128, B_ / 128), 256, SM_TOTAL>>>(
            XA32, w0_f, b0_f, HA32, COUP_, D1_,
            nullptr, nullptr, nullptr, nullptr, nullptr, nullptr, 0);

        // 3) G3 (tf32): HB = relu(HA @ wh0^T + bh0), K=1024
        tf_gemm<1><<<dim3(COUP_ / 128, B_ / 128), 256, SM_TOTAL>>>(
            HA32, wh_f0, bh_f0, HB32, COUP_, COUP_,
            nullptr, nullptr, nullptr, nullptr, nullptr, nullptr, 0);

        // 4) G4 (tf32): HA = relu(HB @ wh1^T + bh1), K=1024
        tf_gemm<1><<<dim3(COUP_ / 128, B_ / 128), 256, SM_TOTAL>>>(
            HB32, wh_f1, bh_f1, HA32, COUP_, COUP_,
            nullptr, nullptr, nullptr, nullptr, nullptr, nullptr, 0);

        // 5) G5 (tf32) + fused coupling (wo row-permuted: cols pair (s_j, t_j))
        tf_gemm<2><<<dim3((2 * D2_) / 128, B_ / 128), 256, SM_TOTAL>>>(
            HA32, wo_f, bo_f, nullptr, 0, COUP_,
            sc_n, off_n, XFnh, XFnl, Xcur, out, last);
    }

    finalize_ld_kernel<<<(B_ + 255) / 256, 256>>>(out);
}

// round 17
// speedup vs baseline: 1.5380x; 1.5380x over previous
#include <cuda_runtime.h>
#include <cuda_bf16.h>
#include <cstdint>
#include <math.h>

// Problem constants
#define B_    8192
#define C_    512
#define F_    8
#define COUP_ 1024
#define NBL_  2
#define D1_   256
#define D2_   256

// ---------------------------------------------------------------------------
// Scratch (device globals — no allocations allowed)
// ---------------------------------------------------------------------------
__device__ float g_X0[B_ * C_];
__device__ float g_X1[B_ * C_];
__device__ float g_LD[B_];
__device__ float g_scale[F_ * C_];
__device__ float g_lssum[F_];

// x-path weights: split-bf16 (G1 stays high precision)
__device__ __nv_bfloat16 g_Wph[F_ * C_ * C_], g_Wpl[F_ * C_ * C_];
// subnet weights: tf32-rounded fp32 (wo ROW-PERMUTED: new 2j = s_j, 2j+1 = t_j)
__device__ float g_w032[F_ * COUP_ * D1_];
__device__ float g_wh32[F_ * NBL_ * COUP_ * COUP_];
__device__ float g_wo32[F_ * 2 * D2_ * COUP_];

// activations: XF split-bf16 ping-pong (x-path); subnet fp32 (tf32-rounded)
__device__ __nv_bfloat16 g_XF0h[B_ * C_], g_XF0l[B_ * C_];
__device__ __nv_bfloat16 g_XF1h[B_ * C_], g_XF1l[B_ * C_];
__device__ float g_XA32[B_ * D1_];
__device__ float g_HA32[B_ * COUP_];
__device__ float g_HB32[B_ * COUP_];

// ---------------------------------------------------------------------------
// Helpers
// ---------------------------------------------------------------------------
__device__ __forceinline__ uint32_t smem_u32(const void* p) {
    uint32_t a;
    asm("{ .reg .u64 t; cvta.to.shared.u64 t, %1; cvt.u32.u64 %0, t; }" : "=r"(a) : "l"(p));
    return a;
}
__device__ __forceinline__ void cpasync16(uint32_t s, const void* g) {
    asm volatile("cp.async.cg.shared.global [%0], [%1], 16;" :: "r"(s), "l"(g) : "memory");
}
__device__ __forceinline__ void cp_commit() { asm volatile("cp.async.commit_group;" ::: "memory"); }
__device__ __forceinline__ void cp_wait0()  { asm volatile("cp.async.wait_group 0;" ::: "memory"); }
__device__ __forceinline__ void cp_wait1()  { asm volatile("cp.async.wait_group 1;" ::: "memory"); }
__device__ __forceinline__ void ldsm4(uint32_t* r, uint32_t addr) {
    asm volatile("ldmatrix.sync.aligned.m8n8.x4.shared.b16 {%0,%1,%2,%3}, [%4];"
                 : "=r"(r[0]), "=r"(r[1]), "=r"(r[2]), "=r"(r[3]) : "r"(addr));
}
__device__ __forceinline__ void mma16816(float* d, const uint32_t* a, const uint32_t* b) {
    asm("mma.sync.aligned.m16n8k16.row.col.f32.bf16.bf16.f32 "
        "{%0,%1,%2,%3}, {%4,%5,%6,%7}, {%8,%9}, {%0,%1,%2,%3};"
        : "+f"(d[0]), "+f"(d[1]), "+f"(d[2]), "+f"(d[3])
        : "r"(a[0]), "r"(a[1]), "r"(a[2]), "r"(a[3]), "r"(b[0]), "r"(b[1]));
}
__device__ __forceinline__ void mma1688t(float* d, const uint32_t* a, const uint32_t* b) {
    asm("mma.sync.aligned.m16n8k8.row.col.f32.tf32.tf32.f32 "
        "{%0,%1,%2,%3}, {%4,%5,%6,%7}, {%8,%9}, {%0,%1,%2,%3};"
        : "+f"(d[0]), "+f"(d[1]), "+f"(d[2]), "+f"(d[3])
        : "r"(a[0]), "r"(a[1]), "r"(a[2]), "r"(a[3]), "r"(b[0]), "r"(b[1]));
}
__device__ __forceinline__ uint32_t pk2(__nv_bfloat16 a, __nv_bfloat16 b) {
    return (uint32_t)__bfloat16_as_ushort(a) | ((uint32_t)__bfloat16_as_ushort(b) << 16);
}
__device__ __forceinline__ void split_store(__nv_bfloat16* hp, __nv_bfloat16* lp,
                                            float a, float b) {
    __nv_bfloat16 ha = __float2bfloat16(a), hb = __float2bfloat16(b);
    *(uint32_t*)hp = pk2(ha, hb);
    *(uint32_t*)lp = pk2(__float2bfloat16(a - __bfloat162float(ha)),
                         __float2bfloat16(b - __bfloat162float(hb)));
}
__device__ __forceinline__ float tf32r(float x) {
    uint32_t u = __float_as_uint(x), o;
    asm("cvt.rna.tf32.f32 %0, %1;" : "=r"(o) : "r"(u));
    return __uint_as_float(o);
}

// smem: both paths use 32KB stages, 3 stages + 512B bias = 98816 -> 2 CTAs/SM
#define TILE_BYTES 8192
#define STAGE_BYTES 32768
#define SM_BIAS_OFF (3 * STAGE_BYTES)
#define SM_TOTAL (SM_BIAS_OFF + 512)

// tf32 smem addressing: 128 rows x 32 fp32 (128B/row); 16B chunk rotation (q+row)&7
__device__ __forceinline__ uint32_t taddr(int row, int kcol) {
    return (uint32_t)(row * 128 + ((((kcol >> 2) + row) & 7) << 4) + ((kcol & 3) << 2));
}

// ---------------------------------------------------------------------------
// G1: split-bf16 GEMM (x-path). X = XF @ Wp^T.
// ---------------------------------------------------------------------------
__global__ __launch_bounds__(256)
void g1_gemm(const __nv_bfloat16* __restrict__ Ah, const __nv_bfloat16* __restrict__ Al,
             const __nv_bfloat16* __restrict__ Bh, const __nv_bfloat16* __restrict__ Bl,
             float* __restrict__ Yf,
             const float* __restrict__ scn, const float* __restrict__ offn,
             __nv_bfloat16* __restrict__ xfnh, __nv_bfloat16* __restrict__ xfnl,
             float* __restrict__ outp, int last) {
    extern __shared__ char smem[];
    const uint32_t sb = smem_u32(smem);
    const int tid  = threadIdx.x;
    const int lane = tid & 31;
    const int wid  = tid >> 5;
    const int warp_m = wid & 3;
    const int warp_n = wid >> 2;
    const int m0 = blockIdx.y * 128;
    const int n0 = blockIdx.x * 128;
    const int K = C_;

    float acc[2][8][4];
#pragma unroll
    for (int mt = 0; mt < 2; mt++)
#pragma unroll
        for (int nt = 0; nt < 8; nt++)
#pragma unroll
            for (int q = 0; q < 4; q++) acc[mt][nt][q] = 0.0f;

    const int nchunks = K >> 5;

    auto prefetch = [&](int st, int kb) {
        uint32_t base = sb + st * STAGE_BYTES;
#pragma unroll
        for (int i = 0; i < 2; i++) {
            int v = tid + i * 256;
            int r = v >> 2, c = v & 3;
            uint32_t sw = (uint32_t)((c ^ ((r >> 1) & 3)) << 4) + r * 64;
            size_t ga = (size_t)(m0 + r) * K + kb + c * 8;
            size_t gb = (size_t)(n0 + r) * K + kb + c * 8;
            cpasync16(base + sw,                  Ah + ga);
            cpasync16(base + TILE_BYTES + sw,     Al + ga);
            cpasync16(base + 2 * TILE_BYTES + sw, Bh + gb);
            cpasync16(base + 3 * TILE_BYTES + sw, Bl + gb);
        }
        cp_commit();
    };

    auto compute = [&](int st) {
        uint32_t base = sb + st * STAGE_BYTES;
#pragma unroll
        for (int ks = 0; ks < 2; ks++) {
            uint32_t ah[2][4], al_[2][4];
#pragma unroll
            for (int mt = 0; mt < 2; mt++) {
                int gq  = lane >> 3;
                int row = warp_m * 32 + mt * 16 + (lane & 7) + (gq & 1) * 8;
                int ch  = ks * 2 + (gq >> 1);
                uint32_t o = row * 64 + ((ch ^ ((row >> 1) & 3)) << 4);
                ldsm4(ah[mt],  base + o);
                ldsm4(al_[mt], base + TILE_BYTES + o);
            }
            uint32_t bh_[4][4], bl_[4][4];
#pragma unroll
            for (int nt = 0; nt < 4; nt++) {
                int row = warp_n * 64 + nt * 16 + (lane & 7) + ((lane >> 4) & 1) * 8;
                int ch  = ks * 2 + ((lane >> 3) & 1);
                uint32_t o = row * 64 + ((ch ^ ((row >> 1) & 3)) << 4);
                ldsm4(bh_[nt], base + 2 * TILE_BYTES + o);
                ldsm4(bl_[nt], base + 3 * TILE_BYTES + o);
            }
#pragma unroll
            for (int mt = 0; mt < 2; mt++)
#pragma unroll
                for (int nt = 0; nt < 4; nt++)
#pragma unroll
                    for (int hf = 0; hf < 2; hf++)
                        mma16816(acc[mt][nt * 2 + hf], ah[mt], &bh_[nt][hf * 2]);
#pragma unroll
            for (int mt = 0; mt < 2; mt++)
#pragma unroll
                for (int nt = 0; nt < 4; nt++)
#pragma unroll
                    for (int hf = 0; hf < 2; hf++)
                        mma16816(acc[mt][nt * 2 + hf], ah[mt], &bl_[nt][hf * 2]);
#pragma unroll
            for (int mt = 0; mt < 2; mt++)
#pragma unroll
                for (int nt = 0; nt < 4; nt++)
#pragma unroll
                    for (int hf = 0; hf < 2; hf++)
                        mma16816(acc[mt][nt * 2 + hf], al_[mt], &bh_[nt][hf * 2]);
        }
    };

    prefetch(0, 0);
    prefetch(1, 32);
    for (int kc = 0; kc < nchunks; kc++) {
        if (kc + 1 < nchunks) cp_wait1();
        else                  cp_wait0();
        __syncthreads();
        if (kc + 2 < nchunks) prefetch((kc + 2) % 3, (kc + 2) * 32);
        compute(kc % 3);
    }

    const int qr  = lane >> 2;
    const int qc2 = (lane & 3) * 2;
#pragma unroll
    for (int mt = 0; mt < 2; mt++) {
        int r0 = m0 + warp_m * 32 + mt * 16 + qr;
        int r1 = r0 + 8;
#pragma unroll
        for (int nt = 0; nt < 8; nt++) {
            float* d = acc[mt][nt];
            int col_g = n0 + warp_n * 64 + nt * 8 + qc2;
            float v00 = d[0], v01 = d[1], v10 = d[2], v11 = d[3];
            *(float2*)(Yf + (size_t)r0 * C_ + col_g) = make_float2(v00, v01);
            *(float2*)(Yf + (size_t)r1 * C_ + col_g) = make_float2(v10, v11);
            if (last) {
                *(float2*)(outp + (size_t)r0 * C_ + col_g) = make_float2(v00, v01);
                *(float2*)(outp + (size_t)r1 * C_ + col_g) = make_float2(v10, v11);
            }
            if (col_g < D1_) {
                *(float2*)(g_XA32 + (size_t)r0 * D1_ + col_g) = make_float2(tf32r(v00), tf32r(v01));
                *(float2*)(g_XA32 + (size_t)r1 * D1_ + col_g) = make_float2(tf32r(v10), tf32r(v11));
                if (!last) {
                    float u00 = fmaf(v00, scn[col_g],     offn[col_g]);
                    float u01 = fmaf(v01, scn[col_g + 1], offn[col_g + 1]);
                    float u10 = fmaf(v10, scn[col_g],     offn[col_g]);
                    float u11 = fmaf(v11, scn[col_g + 1], offn[col_g + 1]);
                    split_store(xfnh + (size_t)r0 * C_ + col_g, xfnl + (size_t)r0 * C_ + col_g, u00, u01);
                    split_store(xfnh + (size_t)r1 * C_ + col_g, xfnl + (size_t)r1 * C_ + col_g, u10, u11);
                }
            }
        }
    }
}

// ---------------------------------------------------------------------------
// tf32 GEMM: MODE 1 = relu + tf32 out; MODE 2 = fused coupling epilogue
// ---------------------------------------------------------------------------
template <int MODE>
__global__ __launch_bounds__(256)
void tf_gemm(const float* __restrict__ A, const float* __restrict__ Bp,
             const float* __restrict__ bias,
             float* __restrict__ Yf, int ldy, int K,
             const float* __restrict__ scn, const float* __restrict__ offn,
             __nv_bfloat16* __restrict__ xfnh, __nv_bfloat16* __restrict__ xfnl,
             const float* __restrict__ Xc,
             float* __restrict__ outp, int last) {
    extern __shared__ char smem[];
    const uint32_t sb = smem_u32(smem);
    const int tid  = threadIdx.x;
    const int lane = tid & 31;
    const int wid  = tid >> 5;
    const int warp_m = wid & 3;
    const int warp_n = wid >> 2;
    const int m0 = blockIdx.y * 128;
    const int n0 = blockIdx.x * 128;
    const int g  = lane >> 2;
    const int tig = lane & 3;

    float* bias_s = (float*)(smem + SM_BIAS_OFF);
    for (int j = tid; j < 128; j += 256) {
        if (MODE == 2) {
            int rn = n0 + j;
            int old = (rn & 1) ? ((rn >> 1) + 256) : (rn >> 1);
            bias_s[j] = bias[old];
        } else {
            bias_s[j] = bias[n0 + j];
        }
    }

    float acc[2][8][4];
#pragma unroll
    for (int mt = 0; mt < 2; mt++)
#pragma unroll
        for (int nt = 0; nt < 8; nt++)
#pragma unroll
            for (int q = 0; q < 4; q++) acc[mt][nt][q] = 0.0f;

    const int nchunks = K >> 5;

    auto prefetch = [&](int st, int kb) {
        uint32_t base = sb + st * STAGE_BYTES;
#pragma unroll
        for (int i = 0; i < 4; i++) {
            int v = tid + i * 256;
            int r = v >> 3, q = v & 7;
            uint32_t dst = (uint32_t)(r * 128 + (((q + r) & 7) << 4));
            cpasync16(base + dst,         A  + (size_t)(m0 + r) * K + kb + q * 4);
            cpasync16(base + 16384 + dst, Bp + (size_t)(n0 + r) * K + kb + q * 4);
        }
        cp_commit();
    };

    auto compute = [&](int st) {
        uint32_t baseA = sb + st * STAGE_BYTES;
        uint32_t baseB = baseA + 16384;
#pragma unroll
        for (int ks = 0; ks < 4; ks++) {
            int k0 = ks * 8 + tig, k2 = k0 + 4;
            uint32_t a[2][4];
#pragma unroll
            for (int mt = 0; mt < 2; mt++) {
                int r = warp_m * 32 + mt * 16 + g;
                a[mt][0] = *(const uint32_t*)(smem + (baseA - sb) + taddr(r,     k0));
                a[mt][1] = *(const uint32_t*)(smem + (baseA - sb) + taddr(r + 8, k0));
                a[mt][2] = *(const uint32_t*)(smem + (baseA - sb) + taddr(r,     k2));
                a[mt][3] = *(const uint32_t*)(smem + (baseA - sb) + taddr(r + 8, k2));
            }
            uint32_t b[8][2];
#pragma unroll
            for (int nt = 0; nt < 8; nt++) {
                int r = warp_n * 64 + nt * 8 + g;
                b[nt][0] = *(const uint32_t*)(smem + (baseB - sb) + taddr(r, k0));
                b[nt][1] = *(const uint32_t*)(smem + (baseB - sb) + taddr(r, k2));
            }
#pragma unroll
            for (int mt = 0; mt < 2; mt++)
#pragma unroll
                for (int nt = 0; nt < 8; nt++)
                    mma1688t(acc[mt][nt], a[mt], b[nt]);
        }
    };

    prefetch(0, 0);
    prefetch(1, 32);
    for (int kc = 0; kc < nchunks; kc++) {
        if (kc + 1 < nchunks) cp_wait1();
        else                  cp_wait0();
        __syncthreads();
        if (kc + 2 < nchunks) prefetch((kc + 2) % 3, (kc + 2) * 32);
        compute(kc % 3);
    }

    const int qr  = lane >> 2;
    const int qc2 = (lane & 3) * 2;
#pragma unroll
    for (int mt = 0; mt < 2; mt++) {
        int r0 = m0 + warp_m * 32 + mt * 16 + qr;
        int r1 = r0 + 8;
        float sum_s0 = 0.0f, sum_s1 = 0.0f;
#pragma unroll
        for (int nt = 0; nt < 8; nt++) {
            float* d = acc[mt][nt];
            int col_l = warp_n * 64 + nt * 8 + qc2;
            int col_g = n0 + col_l;
            if (MODE == 2) {
                int jg = col_g >> 1;
                float bs = bias_s[col_l], bt = bias_s[col_l + 1];
                float s0 = 2.0f * tanhf((d[0] + bs) * 0.1f);
                float t0 = (d[1] + bt) * 0.1f;
                float s1 = 2.0f * tanhf((d[2] + bs) * 0.1f);
                float t1 = (d[3] + bt) * 0.1f;
                float nx0 = Xc[(size_t)r0 * C_ + D1_ + jg] * expf(s0) + t0;
                float nx1 = Xc[(size_t)r1 * C_ + D1_ + jg] * expf(s1) + t1;
                sum_s0 += s0;
                sum_s1 += s1;
                if (!last) {
                    float u0 = fmaf(nx0, scn[D1_ + jg], offn[D1_ + jg]);
                    float u1 = fmaf(nx1, scn[D1_ + jg], offn[D1_ + jg]);
                    __nv_bfloat16 h0 = __float2bfloat16(u0);
                    __nv_bfloat16 h1 = __float2bfloat16(u1);
                    xfnh[(size_t)r0 * C_ + D1_ + jg] = h0;
                    xfnh[(size_t)r1 * C_ + D1_ + jg] = h1;
                    xfnl[(size_t)r0 * C_ + D1_ + jg] = __float2bfloat16(u0 - __bfloat162float(h0));
                    xfnl[(size_t)r1 * C_ + D1_ + jg] = __float2bfloat16(u1 - __bfloat162float(h1));
                } else {
                    outp[(size_t)r0 * C_ + D1_ + jg] = nx0;
                    outp[(size_t)r1 * C_ + D1_ + jg] = nx1;
                }
            } else {
                float bb0 = bias_s[col_l], bb1 = bias_s[col_l + 1];
                float v00 = fmaxf(d[0] + bb0, 0.0f), v01 = fmaxf(d[1] + bb1, 0.0f);
                float v10 = fmaxf(d[2] + bb0, 0.0f), v11 = fmaxf(d[3] + bb1, 0.0f);
                *(float2*)(Yf + (size_t)r0 * ldy + col_g) = make_float2(tf32r(v00), tf32r(v01));
                *(float2*)(Yf + (size_t)r1 * ldy + col_g) = make_float2(tf32r(v10), tf32r(v11));
            }
        }
        if (MODE == 2) {
            sum_s0 += __shfl_xor_sync(0xFFFFFFFFu, sum_s0, 1);
            sum_s0 += __shfl_xor_sync(0xFFFFFFFFu, sum_s0, 2);
            sum_s1 += __shfl_xor_sync(0xFFFFFFFFu, sum_s1, 1);
            sum_s1 += __shfl_xor_sync(0xFFFFFFFFu, sum_s1, 2);
            if ((lane & 3) == 0) {
                atomicAdd(g_LD + r0, sum_s0);
                atomicAdd(g_LD + r1, sum_s1);
            }
        }
    }
}

// ---------------------------------------------------------------------------
// Prep kernels (vectorized float4; merged)
// ---------------------------------------------------------------------------
#define N_WP (F_ * C_ * C_)
#define N_W0 (F_ * COUP_ * D1_)
#define N_WH (F_ * NBL_ * COUP_ * COUP_)
#define N_WO (F_ * 2 * D2_ * COUP_)
#define N_ALLW (N_WP + N_W0 + N_WH + N_WO)

__global__ void prep_weights_kernel(const float* __restrict__ Wp,
                                    const float* __restrict__ w0,
                                    const float* __restrict__ wh,
                                    const float* __restrict__ wo) {
    int i = blockIdx.x * blockDim.x + threadIdx.x;
    int i4 = i * 4;
    if (i4 >= N_ALLW) return;
    int j = i4;
    if (j < N_WP) {
        float4 v = *(const float4*)(Wp + j);
        __nv_bfloat16 h0 = __float2bfloat16(v.x), h1 = __float2bfloat16(v.y);
        __nv_bfloat16 h2 = __float2bfloat16(v.z), h3 = __float2bfloat16(v.w);
        *(uint2*)(g_Wph + j) = make_uint2(pk2(h0, h1), pk2(h2, h3));
        *(uint2*)(g_Wpl + j) = make_uint2(
            pk2(__float2bfloat16(v.x - __bfloat162float(h0)),
                __float2bfloat16(v.y - __bfloat162float(h1))),
            pk2(__float2bfloat16(v.z - __bfloat162float(h2)),
                __float2bfloat16(v.w - __bfloat162float(h3))));
    } else if ((j -= N_WP) < N_W0) {
        float4 v = *(const float4*)(w0 + j);
        *(float4*)(g_w032 + j) = make_float4(tf32r(v.x), tf32r(v.y), tf32r(v.z), tf32r(v.w));
    } else if ((j -= N_W0) < N_WH) {
        float4 v = *(const float4*)(wh + j);
        *(float4*)(g_wh32 + j) = make_float4(tf32r(v.x), tf32r(v.y), tf32r(v.z), tf32r(v.w));
    } else {
        j -= N_WH;
        int f = j / (2 * D2_ * COUP_);
        int rem = j % (2 * D2_ * COUP_);
        int row = rem / COUP_, col = rem % COUP_;
        int rnew = (row < D2_) ? (2 * row) : (2 * (row - D2_) + 1);
        float4 v = *(const float4*)(wo + j);
        *(float4*)(g_wo32 + (size_t)f * 2 * D2_ * COUP_ + (size_t)rnew * COUP_ + col) =
            make_float4(tf32r(v.x), tf32r(v.y), tf32r(v.z), tf32r(v.w));
    }
}

__global__ void prep_scale_kernel(const float* __restrict__ g) {
    int f = blockIdx.x;
    int c = threadIdx.x;
    float gv = g[f * C_ + c];
    float sc = 0.2f * log1pf(expf(0.5f * gv));
    g_scale[f * C_ + c] = sc;
    __shared__ float red[C_];
    red[c] = logf(sc);
    __syncthreads();
    for (int s = C_ / 2; s > 0; s >>= 1) {
        if (c < s) red[c] += red[c + s];
        __syncthreads();
    }
    if (c == 0) g_lssum[f] = red[0];
}

// flow-0 input prep (vectorized) + LD zeroing
__global__ void prep0_full_kernel(const float* __restrict__ z0,
                                  const float* __restrict__ off0) {
    int i = blockIdx.x * blockDim.x + threadIdx.x;
    if (i < B_) g_LD[i] = 0.0f;
    int i4 = i * 4;
    if (i4 < B_ * C_) {
        int c = i4 & (C_ - 1);
        float4 z = *(const float4*)(z0 + i4);
        float4 o = *(const float4*)(off0 + c);
        float4 s = *(const float4*)(g_scale + c);
        float v0 = fmaf(z.x, s.x, o.x), v1 = fmaf(z.y, s.y, o.y);
        float v2 = fmaf(z.z, s.z, o.z), v3 = fmaf(z.w, s.w, o.w);
        __nv_bfloat16 h0 = __float2bfloat16(v0), h1 = __float2bfloat16(v1);
        __nv_bfloat16 h2 = __float2bfloat16(v2), h3 = __float2bfloat16(v3);
        *(uint2*)(g_XF0h + i4) = make_uint2(pk2(h0, h1), pk2(h2, h3));
        *(uint2*)(g_XF0l + i4) = make_uint2(
            pk2(__float2bfloat16(v0 - __bfloat162float(h0)),
                __float2bfloat16(v1 - __bfloat162float(h1))),
            pk2(__float2bfloat16(v2 - __bfloat162float(h2)),
                __float2bfloat16(v3 - __bfloat162float(h3))));
    }
}

__global__ void finalize_ld_kernel(float* __restrict__ out) {
    int r = blockIdx.x * blockDim.x + threadIdx.x;
    if (r < B_) {
        float ls = 0.0f;
#pragma unroll
        for (int f = 0; f < F_; f++) ls += g_lssum[f];
        out[(size_t)B_ * C_ + r] = g_LD[r] + ls;
    }
}

// ---------------------------------------------------------------------------
extern "C" void kernel_launch(void* const* d_in, const int* in_sizes, int n_in,
                              void* d_out, int out_size) {
    const float* z0  = (const float*)d_in[0];
    const float* Wp  = (const float*)d_in[1];
    const float* g   = (const float*)d_in[2];
    const float* off = (const float*)d_in[3];
    const float* w0  = (const float*)d_in[4];
    const float* b0  = (const float*)d_in[5];
    const float* wh  = (const float*)d_in[6];
    const float* bh  = (const float*)d_in[7];
    const float* wo  = (const float*)d_in[8];
    const float* bo  = (const float*)d_in[9];
    float* out = (float*)d_out;

    float *X0, *X1, *scaleP, *XA32, *HA32, *HB32, *w032, *wh32, *wo32;
    __nv_bfloat16 *Wph, *Wpl, *XF0h, *XF0l, *XF1h, *XF1l;
    cudaGetSymbolAddress((void**)&X0, g_X0);
    cudaGetSymbolAddress((void**)&X1, g_X1);
    cudaGetSymbolAddress((void**)&scaleP, g_scale);
    cudaGetSymbolAddress((void**)&Wph, g_Wph); cudaGetSymbolAddress((void**)&Wpl, g_Wpl);
    cudaGetSymbolAddress((void**)&w032, g_w032);
    cudaGetSymbolAddress((void**)&wh32, g_wh32);
    cudaGetSymbolAddress((void**)&wo32, g_wo32);
    cudaGetSymbolAddress((void**)&XF0h, g_XF0h); cudaGetSymbolAddress((void**)&XF0l, g_XF0l);
    cudaGetSymbolAddress((void**)&XF1h, g_XF1h); cudaGetSymbolAddress((void**)&XF1l, g_XF1l);
    cudaGetSymbolAddress((void**)&XA32, g_XA32);
    cudaGetSymbolAddress((void**)&HA32, g_HA32);
    cudaGetSymbolAddress((void**)&HB32, g_HB32);

    cudaFuncSetAttribute(g1_gemm,    cudaFuncAttributeMaxDynamicSharedMemorySize, SM_TOTAL);
    cudaFuncSetAttribute(tf_gemm<1>, cudaFuncAttributeMaxDynamicSharedMemorySize, SM_TOTAL);
    cudaFuncSetAttribute(tf_gemm<2>, cudaFuncAttributeMaxDynamicSharedMemorySize, SM_TOTAL);

    // launch order: 0=prep_scale, 1=prep_weights, 2=prep0,
    //               3=G1, 4=G2, 5=G3 (ncu -s 5 -c 1 lands on the dominant GEMM)
    prep_scale_kernel<<<F_, C_>>>(g);
    prep_weights_kernel<<<(N_ALLW / 4 + 255) / 256, 256>>>(Wp, w0, wh, wo);
    prep0_full_kernel<<<(B_ * C_ / 4 + 255) / 256, 256>>>(z0, off);

    for (int f = 0; f < F_; f++) {
        float* Xcur = (f & 1) ? X1 : X0;
        __nv_bfloat16* XFih = (f & 1) ? XF1h : XF0h;
        __nv_bfloat16* XFil = (f & 1) ? XF1l : XF0l;
        __nv_bfloat16* XFnh = (f & 1) ? XF0h : XF1h;
        __nv_bfloat16* XFnl = (f & 1) ? XF0l : XF1l;

        const __nv_bfloat16* Wph_f = Wph + (size_t)f * C_ * C_;
        const __nv_bfloat16* Wpl_f = Wpl + (size_t)f * C_ * C_;
        const float* w0_f  = w032 + (size_t)f * COUP_ * D1_;
        const float* wh_f0 = wh32 + (size_t)f * NBL_ * COUP_ * COUP_;
        const float* wh_f1 = wh_f0 + (size_t)COUP_ * COUP_;
        const float* wo_f  = wo32 + (size_t)f * 2 * D2_ * COUP_;
        const float* b0_f  = b0 + (size_t)f * COUP_;
        const float* bh_f0 = bh + (size_t)f * NBL_ * COUP_;
        const float* bh_f1 = bh_f0 + COUP_;
        const float* bo_f  = bo + (size_t)f * 2 * D2_;

        int last = (f == F_ - 1) ? 1 : 0;
        const float* sc_n  = scaleP + (size_t)((f + 1) % F_) * C_;
        const float* off_n = off + (size_t)((f + 1) % F_) * C_;

        // 1) G1 (split-bf16): X = XF @ Wp^T
        g1_gemm<<<dim3(C_ / 128, B_ / 128), 256, SM_TOTAL>>>(
            XFih, XFil, Wph_f, Wpl_f, Xcur,
            sc_n, off_n, XFnh, XFnl, out, last);

        // 2) G2 (tf32): HA = relu(x1 @ w0^T + b0), K=256
        tf_gemm<1><<<dim3(COUP_ / 128, B_ / 128), 256, SM_TOTAL>>>(
            XA32, w0_f, b0_f, HA32, COUP_, D1_,
            nullptr, nullptr, nullptr, nullptr, nullptr, nullptr, 0);

        // 3) G3 (tf32): HB = relu(HA @ wh0^T + bh0), K=1024
        tf_gemm<1><<<dim3(COUP_ / 128, B_ / 128), 256, SM_TOTAL>>>(
            HA32, wh_f0, bh_f0, HB32, COUP_, COUP_,
            nullptr, nullptr, nullptr, nullptr, nullptr, nullptr, 0);

        // 4) G4 (tf32): HA = relu(HB @ wh1^T + bh1), K=1024
        tf_gemm<1><<<dim3(COUP_ / 128, B_ / 128), 256, SM_TOTAL>>>(
            HB32, wh_f1, bh_f1, HA32, COUP_, COUP_,
            nullptr, nullptr, nullptr, nullptr, nullptr, nullptr, 0);

        // 5) G5 (tf32) + fused coupling (wo row-permuted: cols pair (s_j, t_j))
        tf_gemm<2><<<dim3((2 * D2_) / 128, B_ / 128), 256, SM_TOTAL>>>(
            HA32, wo_f, bo_f, nullptr, 0, COUP_,
            sc_n, off_n, XFnh, XFnl, Xcur, out, last);
    }

    finalize_ld_kernel<<<(B_ + 255) / 256, 256>>>(out);
}